// round 15
// baseline (speedup 1.0000x reference)
#include <cuda_runtime.h>
#include <cuda_bf16.h>
#include <math.h>

#define B_ 8
#define C_ 256
#define T_ 2048
#define DEPTH_ 256
#define OCH 384
#define SSTR 322                /* even -> 8B-aligned paired loads */
#define SS_F (64*SSTR)
#define SM_F (SS_F + 6144)      /* 107008 B -> 2 CTA/SM */

typedef unsigned long long u64t;

__device__ __nv_bfloat16 g_Whi[OCH*C_];   // [o][c] bf16 hi
__device__ __nv_bfloat16 g_Wlo[OCH*C_];   // [o][c] bf16 lo (residual)
__device__ float g_bf[OCH];
__device__ float g_qkv[B_*T_*OCH];    // V region (+128..383) written/read
__device__ float g_qkT[B_*128*T_];    // [b][o][t]: o<64 q*0.125, o>=64 k
__device__ float g_denom[T_];

static __device__ __forceinline__ u64t pk2(float a,float b){u64t r;asm("mov.b64 %0,{%1,%2};":"=l"(r):"f"(a),"f"(b));return r;}
static __device__ __forceinline__ u64t dup2(float a){return pk2(a,a);}
static __device__ __forceinline__ void fma2(u64t&d,u64t a,u64t b){asm("fma.rn.f32x2 %0,%1,%2,%3;":"=l"(d):"l"(a),"l"(b),"l"(d));}
static __device__ __forceinline__ void unpk(u64t v,float&x,float&y){asm("mov.b64 {%0,%1},%2;":"=f"(x),"=f"(y):"l"(v));}
static __device__ __forceinline__ unsigned smem_u32(const void* p){
    unsigned a; asm("{ .reg .u64 t; cvta.to.shared.u64 t, %1; cvt.u32.u64 %0, t; }":"=r"(a):"l"(p)); return a;
}
static __device__ __forceinline__ void cpa16(unsigned dst, const void* src){
    asm volatile("cp.async.cg.shared.global [%0], [%1], 16;" :: "r"(dst), "l"(src));
}
#define CPCOMMIT asm volatile("cp.async.commit_group;" ::: "memory")
#define CPWAIT0  asm volatile("cp.async.wait_group 0;" ::: "memory")

static __device__ __forceinline__ unsigned pkbf(float a, float b){
    return (unsigned)__bfloat16_as_ushort(__float2bfloat16_rn(a))
         | ((unsigned)__bfloat16_as_ushort(__float2bfloat16_rn(b)) << 16);
}
static __device__ __forceinline__ float bfres(float a){
    return a - __bfloat162float(__float2bfloat16_rn(a));
}
#define MMA_BF16(d,a,b2) asm volatile( \
    "mma.sync.aligned.m16n8k16.row.col.f32.bf16.bf16.f32 " \
    "{%0,%1,%2,%3},{%4,%5,%6,%7},{%8,%9},{%0,%1,%2,%3};" \
    : "+f"((d)[0]),"+f"((d)[1]),"+f"((d)[2]),"+f"((d)[3]) \
    : "r"((a)[0]),"r"((a)[1]),"r"((a)[2]),"r"((a)[3]),"r"((b2)[0]),"r"((b2)[1]))

// ---------------------------------------------------------------------------
// Fold BN into weights; emit bf16 hi/lo in [o][c] layout + bias.
// ---------------------------------------------------------------------------
__global__ void fold_k(
    const float* __restrict__ kW,const float* __restrict__ kb,const float* __restrict__ kg,
    const float* __restrict__ kbe,const float* __restrict__ kmu,const float* __restrict__ kva,
    const float* __restrict__ qW,const float* __restrict__ qb,const float* __restrict__ qg,
    const float* __restrict__ qbe,const float* __restrict__ qmu,const float* __restrict__ qva,
    const float* __restrict__ vW,const float* __restrict__ vb,const float* __restrict__ vg,
    const float* __restrict__ vbe,const float* __restrict__ vmu,const float* __restrict__ vva)
{
    int c = blockIdx.x, o = threadIdx.x;
    const float *W,*bb,*gg,*be,*mu,*va; int oo;
    if (o < 64)       { W=qW;bb=qb;gg=qg;be=qbe;mu=qmu;va=qva;oo=o; }
    else if (o < 128) { W=kW;bb=kb;gg=kg;be=kbe;mu=kmu;va=kva;oo=o-64; }
    else              { W=vW;bb=vb;gg=vg;be=vbe;mu=vmu;va=vva;oo=o-128; }
    float inv = gg[oo]*rsqrtf(va[oo]+1e-5f);
    float w = W[oo*C_+c]*inv;
    __nv_bfloat16 hi = __float2bfloat16_rn(w);
    g_Whi[o*C_+c] = hi;
    g_Wlo[o*C_+c] = __float2bfloat16_rn(w - __bfloat162float(hi));
    if (c == 0) g_bf[o] = (bb[oo]-mu[oo])*inv + be[oo];
}

// ---------------------------------------------------------------------------
// Projection via mma.sync bf16 hi/lo split (tensor pipe, no 'a'-gated insts).
// CTA: 128 t x 64 o, 256 thr (8 warps: warp tile 32o x 32t). grid (16,6,8).
// D[o][t] = W[o][c] @ x[c][t]; A = W row-major (k-pairs natural),
// B = x staged to smem as bf16x2 pairs via shfl-exchange.
// ---------------------------------------------------------------------------
__global__ __launch_bounds__(256) void proj_t(const float* __restrict__ x)
{
    __shared__ unsigned psm[8704];               // 34816 B
    unsigned* Xhi = psm;                         // [128 t][34] bf16x2 (c-pairs)
    unsigned* Xlo = psm + 4352;
    float*    Vst = (float*)psm;                 // [128 t][68] epilogue alias

    const int t0 = blockIdx.x*128, o0 = blockIdx.y*64, b = blockIdx.z;
    const int tid = threadIdx.x, w = tid>>5, lane = tid&31;
    const int ow = o0 + (w&1)*32;                // warp o base
    const int twl = (w>>1)*32;                   // warp t base (local)
    const int l4 = lane>>2, m4 = lane&3;

    float acc[2][4][4];
    #pragma unroll
    for (int mt=0;mt<2;mt++)
        #pragma unroll
        for (int nt=0;nt<4;nt++)
            #pragma unroll
            for (int i=0;i<4;i++) acc[mt][nt][i] = 0.f;

    for (int kc = 0; kc < 4; kc++) {             // 64-c chunks
        __syncthreads();
        {   // stage x[kc*64..+63][t0..t0+127] as bf16x2 hi/lo pairs
            int half = lane>>4, l15 = lane&15;
            #pragma unroll
            for (int it=0; it<8; it++){
                int task = w + it*8;             // 0..63
                int c2 = task & 31, tseg = task >> 5;
                int c = kc*64 + c2*2 + half;
                float4 v = *(const float4*)&x[((size_t)b*C_ + c)*T_ + t0 + tseg*64 + l15*4];
                float4 ot;
                ot.x = __shfl_xor_sync(0xffffffffu, v.x, 16);
                ot.y = __shfl_xor_sync(0xffffffffu, v.y, 16);
                ot.z = __shfl_xor_sync(0xffffffffu, v.z, 16);
                ot.w = __shfl_xor_sync(0xffffffffu, v.w, 16);
                int tb = tseg*64 + l15*4;
                if (half == 0) {                 // v=row c, ot=row c+1 -> hi
                    Xhi[(tb+0)*34 + c2] = pkbf(v.x, ot.x);
                    Xhi[(tb+1)*34 + c2] = pkbf(v.y, ot.y);
                    Xhi[(tb+2)*34 + c2] = pkbf(v.z, ot.z);
                    Xhi[(tb+3)*34 + c2] = pkbf(v.w, ot.w);
                } else {                         // v=row c+1, ot=row c -> lo
                    Xlo[(tb+0)*34 + c2] = pkbf(bfres(ot.x), bfres(v.x));
                    Xlo[(tb+1)*34 + c2] = pkbf(bfres(ot.y), bfres(v.y));
                    Xlo[(tb+2)*34 + c2] = pkbf(bfres(ot.z), bfres(v.z));
                    Xlo[(tb+3)*34 + c2] = pkbf(bfres(ot.w), bfres(v.w));
                }
            }
        }
        __syncthreads();

        #pragma unroll
        for (int k16 = 0; k16 < 4; k16++) {      // 16-c mma steps
            unsigned ah[2][4], al[2][4], bh[4][2], bl[4][2];
            int c = kc*64 + k16*16 + m4*2;
            #pragma unroll
            for (int mt=0; mt<2; mt++){
                int oa = ow + mt*16 + l4;
                ah[mt][0] = *(const unsigned*)&g_Whi[oa*C_ + c];
                ah[mt][1] = *(const unsigned*)&g_Whi[(oa+8)*C_ + c];
                ah[mt][2] = *(const unsigned*)&g_Whi[oa*C_ + c + 8];
                ah[mt][3] = *(const unsigned*)&g_Whi[(oa+8)*C_ + c + 8];
                al[mt][0] = *(const unsigned*)&g_Wlo[oa*C_ + c];
                al[mt][1] = *(const unsigned*)&g_Wlo[(oa+8)*C_ + c];
                al[mt][2] = *(const unsigned*)&g_Wlo[oa*C_ + c + 8];
                al[mt][3] = *(const unsigned*)&g_Wlo[(oa+8)*C_ + c + 8];
            }
            #pragma unroll
            for (int nt=0; nt<4; nt++){
                int trow = twl + nt*8 + l4;
                int c2 = k16*8 + m4;
                bh[nt][0] = Xhi[trow*34 + c2];
                bh[nt][1] = Xhi[trow*34 + c2 + 4];
                bl[nt][0] = Xlo[trow*34 + c2];
                bl[nt][1] = Xlo[trow*34 + c2 + 4];
            }
            #pragma unroll
            for (int mt=0; mt<2; mt++)
                #pragma unroll
                for (int nt=0; nt<4; nt++){
                    MMA_BF16(acc[mt][nt], ah[mt], bh[nt]);
                    MMA_BF16(acc[mt][nt], ah[mt], bl[nt]);
                    MMA_BF16(acc[mt][nt], al[mt], bh[nt]);
                }
        }
    }

    // ---- epilogue ----
    if (o0 < 128) {          // q/k: write transposed [o][t], q scaled 0.125
        float sc = (o0 == 0) ? 0.125f : 1.f;
        #pragma unroll
        for (int mt=0; mt<2; mt++)
            #pragma unroll
            for (int h=0; h<2; h++){
                int o = ow + mt*16 + l4 + 8*h;
                float bi = g_bf[o];
                float* dst = &g_qkT[((size_t)b*128 + o)*T_];
                #pragma unroll
                for (int nt=0; nt<4; nt++){
                    int t = t0 + twl + nt*8 + m4*2;
                    float2 vv;
                    vv.x = fmaxf(acc[mt][nt][2*h]   + bi, 0.f)*sc;
                    vv.y = fmaxf(acc[mt][nt][2*h+1] + bi, 0.f)*sc;
                    *(float2*)&dst[t] = vv;
                }
            }
    } else {                 // v: smem transpose -> coalesced [t][384]
        __syncthreads();
        #pragma unroll
        for (int mt=0; mt<2; mt++)
            #pragma unroll
            for (int h=0; h<2; h++){
                int ol = (w&1)*32 + mt*16 + l4 + 8*h;
                float bi = g_bf[o0 + ol];
                #pragma unroll
                for (int nt=0; nt<4; nt++){
                    int tl = twl + nt*8 + m4*2;
                    Vst[tl*68 + ol]     = fmaxf(acc[mt][nt][2*h]   + bi, 0.f);
                    Vst[(tl+1)*68 + ol] = fmaxf(acc[mt][nt][2*h+1] + bi, 0.f);
                }
            }
        __syncthreads();
        #pragma unroll
        for (int it=0; it<8; it++){
            int idx = tid + it*256;
            int t = idx>>4, og = (idx&15)*4;
            float4 v = *(const float4*)&Vst[t*68 + og];
            *(float4*)&g_qkv[((size_t)b*T_ + t0 + t)*OCH + o0 + og] = v;
        }
    }
}

// ---------------------------------------------------------------------------
// Denominator: batch 0, 16-row tiles, grid 128, 256 thr (warp = 2 rows).
// ---------------------------------------------------------------------------
__global__ __launch_bounds__(256) void denom_k()
{
    __shared__ float Ss[16*SSTR];
    __shared__ float Qp[64*16];
    __shared__ float Kt[2*64*32];
    const int t0 = blockIdx.x*16;
    const int tid = threadIdx.x, warp = tid>>5, lane = tid&31;
    const int r0 = warp*2;
    const int sbase = t0 - DEPTH_;
    const int jmin = (t0 < DEPTH_) ? DEPTH_ - t0 : 0;
    const float* qT = g_qkT;     // batch 0
    const unsigned qp_u = smem_u32(Qp), kt_u = smem_u32(Kt);

    { int d = tid>>2, c4 = (tid&3)*4;
      cpa16(qp_u + (unsigned)(d*16 + c4)*4u, qT + (size_t)d*T_ + t0 + c4); }
    const int chs = jmin >> 5;
    #pragma unroll
    for (int i=0;i<2;i++){
        int f = tid + i*256, d = f>>3, c4 = (f&7)*4;
        cpa16(kt_u + (unsigned)((chs&1)*2048 + d*32 + c4)*4u,
              qT + (size_t)(64+d)*T_ + sbase + chs*32 + c4);
    }
    CPCOMMIT;

    for (int ch = chs; ch < 9; ch++) {
        CPWAIT0; __syncthreads();
        if (ch + 1 < 9) {
            #pragma unroll
            for (int i=0;i<2;i++){
                int f = tid + i*256, d = f>>3, c4 = (f&7)*4;
                cpa16(kt_u + (unsigned)(((ch+1)&1)*2048 + d*32 + c4)*4u,
                      qT + (size_t)(64+d)*T_ + sbase + (ch+1)*32 + c4);
            }
            CPCOMMIT;
        }
        const float* Kb = Kt + (ch&1)*2048;
        u64t a0 = 0ull;
        #pragma unroll 8
        for (int d = 0; d < 64; d++) {
            u64t qq = *(const u64t*)&Qp[d*16 + r0];
            u64t kk = dup2(Kb[d*32 + lane]);
            fma2(a0, qq, kk);
        }
        float f0,f1; unpk(a0,f0,f1);
        int c = ch*32 + lane;
        Ss[(r0+0)*SSTR+c]=f0; Ss[(r0+1)*SSTR+c]=f1;
    }
    __syncthreads();

    {
        int r = tid>>4, g = tid&15, t = t0 + r;
        int jlo = (r+1 > jmin) ? r+1 : jmin;
        int jhi = r + DEPTH_;
        float mx = 0.f;
        for (int j = jlo + g; j <= jhi; j += 16)
            mx = fmaxf(mx, Ss[r*SSTR + j]);
        mx = fmaxf(mx, __shfl_xor_sync(0xffffffffu, mx, 1));
        mx = fmaxf(mx, __shfl_xor_sync(0xffffffffu, mx, 2));
        mx = fmaxf(mx, __shfl_xor_sync(0xffffffffu, mx, 4));
        mx = fmaxf(mx, __shfl_xor_sync(0xffffffffu, mx, 8));
        float s = 0.f;
        for (int j = jlo + g; j <= jhi; j += 16)
            s += __expf(Ss[r*SSTR + j] - mx);
        s += __shfl_xor_sync(0xffffffffu, s, 1);
        s += __shfl_xor_sync(0xffffffffu, s, 2);
        s += __shfl_xor_sync(0xffffffffu, s, 4);
        s += __shfl_xor_sync(0xffffffffu, s, 8);
        if (g == 0) g_denom[t] = s + 1e-30f;
    }
}

// ---------------------------------------------------------------------------
// Banded attention: 64-row tile, 512 thr, 2 CTA/SM (R11 structure).
// ---------------------------------------------------------------------------
__global__ __launch_bounds__(512,2) void attn_k(const float* __restrict__ x,
                                                float* __restrict__ y)
{
    extern __shared__ float sm[];
    float* Ss = sm;                 // [64][322]
    float* Qp = sm + SS_F;          // [64 d][64 t]
    float* Kt = Qp + 4096;          // [64 d][32 c]
    float* Vs = sm + SS_F;          // [16 s][256 c] (alias Qp)

    const int t0 = blockIdx.x*64;
    const int b  = blockIdx.y;
    const int tid = threadIdx.x, warp = tid>>5, lane = tid&31;
    const int r0 = warp*4;
    const int sbase = t0 - DEPTH_;
    const int jmin = (t0 < DEPTH_) ? DEPTH_ - t0 : 0;
    const float* qT = g_qkT + (size_t)b*128*T_;
    const unsigned qp_u = smem_u32(Qp);

    #pragma unroll
    for (int i=0;i<2;i++){
        int u = tid + i*512, d = u>>4, c4 = u&15;
        cpa16(qp_u + (unsigned)(d*64 + c4*4)*4u, qT + (size_t)d*T_ + t0 + c4*4);
    }
    CPCOMMIT;

    const int chs = jmin >> 5;
    const int kd = tid>>3, kc4 = (tid&7)*4;
    float4 kreg = *(const float4*)&qT[(size_t)(64+kd)*T_ + sbase + chs*32 + kc4];
    CPWAIT0;

    for (int ch = chs; ch < 10; ch++) {
        __syncthreads();
        *(float4*)&Kt[kd*32 + kc4] = kreg;
        if (ch + 1 < 10)
            kreg = *(const float4*)&qT[(size_t)(64+kd)*T_ + sbase + (ch+1)*32 + kc4];
        __syncthreads();
        u64t a0 = 0ull, a1 = 0ull;
        #pragma unroll 8
        for (int d = 0; d < 64; d++) {
            float4 qf = *(const float4*)&Qp[d*64 + r0];
            ulonglong2 qq = *(ulonglong2*)&qf;
            u64t kk = dup2(Kt[d*32 + lane]);
            fma2(a0, qq.x, kk); fma2(a1, qq.y, kk);
        }
        float f0,f1,f2,f3; unpk(a0,f0,f1); unpk(a1,f2,f3);
        int c = ch*32 + lane;
        Ss[(r0+0)*SSTR+c]=f0; Ss[(r0+1)*SSTR+c]=f1;
        Ss[(r0+2)*SSTR+c]=f2; Ss[(r0+3)*SSTR+c]=f3;
    }
    __syncthreads();

    const int ch16 = jmin >> 4;
    const int vrow = tid>>6, vc4 = (tid&63)*4;
    float4 vr0 = *(const float4*)&g_qkv[((size_t)b*T_ + sbase + ch16*16 + vrow)*OCH + 128 + vc4];
    float4 vr1 = *(const float4*)&g_qkv[((size_t)b*T_ + sbase + ch16*16 + vrow + 8)*OCH + 128 + vc4];

    {
        int r = tid>>3, g = tid&7, t = t0 + r;
        int jlo = (r+1 > jmin) ? r+1 : jmin;
        int jhi = r + DEPTH_;
        float mx = 0.f;
        for (int j = jlo + g; j <= jhi; j += 8)
            mx = fmaxf(mx, Ss[r*SSTR + j]);
        mx = fmaxf(mx, __shfl_xor_sync(0xffffffffu, mx, 1));
        mx = fmaxf(mx, __shfl_xor_sync(0xffffffffu, mx, 2));
        mx = fmaxf(mx, __shfl_xor_sync(0xffffffffu, mx, 4));
        float invd = 1.f / g_denom[t];
        for (int j = g; j < 320; j += 8) {
            float v = Ss[r*SSTR + j];
            Ss[r*SSTR + j] = (j >= jlo && j <= jhi) ? __expf(v - mx)*invd : 0.f;
        }
    }

    const int rg = warp >> 1, cg = warp & 1;
    const int r0p = rg * 8;
    const int cL = cg*128 + lane*4;
    const int jAw0 = (r0p+1 > jmin) ? r0p+1 : jmin;
    const int jAw = jAw0 & ~1;
    const int jBw = r0p + 7 + DEPTH_;
    u64t acc[8][2];
    #pragma unroll
    for (int i=0;i<8;i++){ acc[i][0]=0ull; acc[i][1]=0ull; }

    for (int ch = ch16; ch < 20; ch++) {
        __syncthreads();
        *(float4*)&Vs[vrow*256 + vc4]       = vr0;
        *(float4*)&Vs[(vrow+8)*256 + vc4]   = vr1;
        if (ch + 1 < 20) {
            vr0 = *(const float4*)&g_qkv[((size_t)b*T_ + sbase + (ch+1)*16 + vrow)*OCH + 128 + vc4];
            vr1 = *(const float4*)&g_qkv[((size_t)b*T_ + sbase + (ch+1)*16 + vrow + 8)*OCH + 128 + vc4];
        }
        __syncthreads();
        int c0 = ch*16;
        int bs = (c0 > jAw) ? c0 : jAw;
        int be = (c0+14 < jBw) ? c0+14 : jBw;
        for (int j2 = bs; j2 <= be; j2 += 2) {
            int lr = j2 - c0;
            float4 v0 = *(const float4*)&Vs[lr*256 + cL];
            float4 v1 = *(const float4*)&Vs[(lr+1)*256 + cL];
            ulonglong2 vp0 = *(ulonglong2*)&v0, vp1 = *(ulonglong2*)&v1;
            #pragma unroll
            for (int i = 0; i < 8; i += 2) {
                float2 pa = *(const float2*)&Ss[(r0p+i)*SSTR + j2];
                float2 pb = *(const float2*)&Ss[(r0p+i+1)*SSTR + j2];
                u64t da = dup2(pa.x), db = dup2(pb.x);
                fma2(acc[i][0],   da, vp0.x); fma2(acc[i][1],   da, vp0.y);
                fma2(acc[i+1][0], db, vp0.x); fma2(acc[i+1][1], db, vp0.y);
                da = dup2(pa.y); db = dup2(pb.y);
                fma2(acc[i][0],   da, vp1.x); fma2(acc[i][1],   da, vp1.y);
                fma2(acc[i+1][0], db, vp1.x); fma2(acc[i+1][1], db, vp1.y);
            }
        }
    }

    float o_[8][4];
    #pragma unroll
    for (int i=0;i<8;i++){
        unpk(acc[i][0], o_[i][0], o_[i][1]);
        unpk(acc[i][1], o_[i][2], o_[i][3]);
    }
    #pragma unroll
    for (int k=0;k<4;k++){
        size_t gi = ((size_t)b*C_ + cL + k)*T_ + t0 + r0p;
        float4 xa = *(const float4*)&x[gi];
        float4 o4 = make_float4(xa.x + o_[0][k], xa.y + o_[1][k],
                                xa.z + o_[2][k], xa.w + o_[3][k]);
        *(float4*)&y[gi] = o4;
        float4 xb = *(const float4*)&x[gi + 4];
        float4 o5 = make_float4(xb.x + o_[4][k], xb.y + o_[5][k],
                                xb.z + o_[6][k], xb.w + o_[7][k]);
        *(float4*)&y[gi + 4] = o5;
    }
}

// ---------------------------------------------------------------------------
extern "C" void kernel_launch(void* const* d_in, const int* in_sizes, int n_in,
                              void* d_out, int out_size)
{
    const float* x   = (const float*)d_in[0];
    const float* kW  = (const float*)d_in[1];
    const float* kb  = (const float*)d_in[2];
    const float* kg  = (const float*)d_in[3];
    const float* kbe = (const float*)d_in[4];
    const float* kmu = (const float*)d_in[5];
    const float* kva = (const float*)d_in[6];
    const float* qW  = (const float*)d_in[7];
    const float* qb  = (const float*)d_in[8];
    const float* qg  = (const float*)d_in[9];
    const float* qbe = (const float*)d_in[10];
    const float* qmu = (const float*)d_in[11];
    const float* qva = (const float*)d_in[12];
    const float* vW  = (const float*)d_in[13];
    const float* vb  = (const float*)d_in[14];
    const float* vg  = (const float*)d_in[15];
    const float* vbe = (const float*)d_in[16];
    const float* vmu = (const float*)d_in[17];
    const float* vva = (const float*)d_in[18];
    float* y = (float*)d_out;

    cudaFuncSetAttribute(attn_k, cudaFuncAttributeMaxDynamicSharedMemorySize, SM_F*(int)sizeof(float));

    fold_k<<<C_, OCH>>>(kW,kb,kg,kbe,kmu,kva, qW,qb,qg,qbe,qmu,qva, vW,vb,vg,vbe,vmu,vva);
    proj_t<<<dim3(T_/128, OCH/64, B_), 256>>>(x);
    denom_k<<<T_/16, 256>>>();
    attn_k<<<dim3(T_/64, B_), 512, SM_F*sizeof(float)>>>(x, y);
}

// round 16
// speedup vs baseline: 1.1720x; 1.1720x over previous
#include <cuda_runtime.h>
#include <cuda_bf16.h>
#include <math.h>

#define B_ 8
#define C_ 256
#define T_ 2048
#define DEPTH_ 256
#define OCH 384
#define SSTR 322                /* even -> 8B-aligned paired loads */
#define SS_F (64*SSTR)
#define SM_F (SS_F + 6144)      /* 107008 B -> 2 CTA/SM */

/* proj_t smem layout (bytes): W rows padded to 528B (conflict-free A LDS) */
#define WSTR 528
#define PW_HI 0
#define PW_LO 33792
#define PX_HI 67584
#define PX_LO 84992
#define PJ_SMEM 102400          /* 100 KB -> 2 CTA/SM */

typedef unsigned long long u64t;

__device__ __nv_bfloat16 g_Whi[OCH*C_];   // [o][c] bf16 hi
__device__ __nv_bfloat16 g_Wlo[OCH*C_];   // [o][c] bf16 lo (residual)
__device__ float g_bf[OCH];
__device__ float g_qkv[B_*T_*OCH];    // V region (+128..383) written/read
__device__ float g_qkT[B_*128*T_];    // [b][o][t]: o<64 q*0.125, o>=64 k
__device__ float g_denom[T_];

static __device__ __forceinline__ u64t pk2(float a,float b){u64t r;asm("mov.b64 %0,{%1,%2};":"=l"(r):"f"(a),"f"(b));return r;}
static __device__ __forceinline__ u64t dup2(float a){return pk2(a,a);}
static __device__ __forceinline__ void fma2(u64t&d,u64t a,u64t b){asm("fma.rn.f32x2 %0,%1,%2,%3;":"=l"(d):"l"(a),"l"(b),"l"(d));}
static __device__ __forceinline__ void unpk(u64t v,float&x,float&y){asm("mov.b64 {%0,%1},%2;":"=f"(x),"=f"(y):"l"(v));}
static __device__ __forceinline__ unsigned smem_u32(const void* p){
    unsigned a; asm("{ .reg .u64 t; cvta.to.shared.u64 t, %1; cvt.u32.u64 %0, t; }":"=r"(a):"l"(p)); return a;
}
static __device__ __forceinline__ void cpa16(unsigned dst, const void* src){
    asm volatile("cp.async.cg.shared.global [%0], [%1], 16;" :: "r"(dst), "l"(src));
}
#define CPCOMMIT asm volatile("cp.async.commit_group;" ::: "memory")
#define CPWAIT0  asm volatile("cp.async.wait_group 0;" ::: "memory")

static __device__ __forceinline__ unsigned pkbf(float a, float b){
    return (unsigned)__bfloat16_as_ushort(__float2bfloat16_rn(a))
         | ((unsigned)__bfloat16_as_ushort(__float2bfloat16_rn(b)) << 16);
}
static __device__ __forceinline__ float bfres(float a){
    return a - __bfloat162float(__float2bfloat16_rn(a));
}
#define MMA_BF16(d,a,b2) asm volatile( \
    "mma.sync.aligned.m16n8k16.row.col.f32.bf16.bf16.f32 " \
    "{%0,%1,%2,%3},{%4,%5,%6,%7},{%8,%9},{%0,%1,%2,%3};" \
    : "+f"((d)[0]),"+f"((d)[1]),"+f"((d)[2]),"+f"((d)[3]) \
    : "r"((a)[0]),"r"((a)[1]),"r"((a)[2]),"r"((a)[3]),"r"((b2)[0]),"r"((b2)[1]))

// ---------------------------------------------------------------------------
// Fold BN into weights; emit bf16 hi/lo in [o][c] layout + bias.
// ---------------------------------------------------------------------------
__global__ void fold_k(
    const float* __restrict__ kW,const float* __restrict__ kb,const float* __restrict__ kg,
    const float* __restrict__ kbe,const float* __restrict__ kmu,const float* __restrict__ kva,
    const float* __restrict__ qW,const float* __restrict__ qb,const float* __restrict__ qg,
    const float* __restrict__ qbe,const float* __restrict__ qmu,const float* __restrict__ qva,
    const float* __restrict__ vW,const float* __restrict__ vb,const float* __restrict__ vg,
    const float* __restrict__ vbe,const float* __restrict__ vmu,const float* __restrict__ vva)
{
    int c = blockIdx.x, o = threadIdx.x;
    const float *W,*bb,*gg,*be,*mu,*va; int oo;
    if (o < 64)       { W=qW;bb=qb;gg=qg;be=qbe;mu=qmu;va=qva;oo=o; }
    else if (o < 128) { W=kW;bb=kb;gg=kg;be=kbe;mu=kmu;va=kva;oo=o-64; }
    else              { W=vW;bb=vb;gg=vg;be=vbe;mu=vmu;va=vva;oo=o-128; }
    float inv = gg[oo]*rsqrtf(va[oo]+1e-5f);
    float w = W[oo*C_+c]*inv;
    __nv_bfloat16 hi = __float2bfloat16_rn(w);
    g_Whi[o*C_+c] = hi;
    g_Wlo[o*C_+c] = __float2bfloat16_rn(w - __bfloat162float(hi));
    if (c == 0) g_bf[o] = (bb[oo]-mu[oo])*inv + be[oo];
}

// ---------------------------------------------------------------------------
// Projection via mma.sync bf16 hi/lo split. CTA: 128 t x 64 o, 256 thr.
// W tile staged ONCE to smem via coalesced cp.async (R15 fix: was per-step
// scattered global LDG). A-frag LDS conflict-free via 528B row padding.
// ---------------------------------------------------------------------------
__global__ __launch_bounds__(256) void proj_t(const float* __restrict__ x)
{
    extern __shared__ char psm[];
    unsigned* Xhi = (unsigned*)(psm + PX_HI);    // [128 t][34] bf16x2 c-pairs
    unsigned* Xlo = (unsigned*)(psm + PX_LO);
    float*    Vst = (float*)(psm + PX_HI);       // [128 t][68] epilogue alias

    const int t0 = blockIdx.x*128, o0 = blockIdx.y*64, b = blockIdx.z;
    const int tid = threadIdx.x, w = tid>>5, lane = tid&31;
    const int ow = (w&1)*32;                     // warp o base (local)
    const int twl = (w>>1)*32;                   // warp t base (local)
    const int l4 = lane>>2, m4 = lane&3;
    const unsigned sb = smem_u32(psm);

    // ---- stage W tile (hi+lo, 64 o x 256 c) once, coalesced ----
    {
        const char* whs = (const char*)(g_Whi + (size_t)o0*C_);
        const char* wls = (const char*)(g_Wlo + (size_t)o0*C_);
        #pragma unroll
        for (int i=0;i<8;i++){
            int idx = tid + i*256;               // 0..2047
            int row = idx>>5, c16 = idx&31;
            cpa16(sb + PW_HI + row*WSTR + c16*16, whs + row*512 + c16*16);
            cpa16(sb + PW_LO + row*WSTR + c16*16, wls + row*512 + c16*16);
        }
        CPCOMMIT;
    }

    float acc[2][4][4];
    #pragma unroll
    for (int mt=0;mt<2;mt++)
        #pragma unroll
        for (int nt=0;nt<4;nt++)
            #pragma unroll
            for (int i=0;i<4;i++) acc[mt][nt][i] = 0.f;

    for (int kc = 0; kc < 4; kc++) {             // 64-c chunks
        __syncthreads();
        {   // stage x[kc*64..+63][t0..t0+127] as bf16x2 hi/lo pairs
            int half = lane>>4, l15 = lane&15;
            #pragma unroll
            for (int it=0; it<8; it++){
                int task = w + it*8;             // 0..63
                int c2 = task & 31, tseg = task >> 5;
                int c = kc*64 + c2*2 + half;
                float4 v = *(const float4*)&x[((size_t)b*C_ + c)*T_ + t0 + tseg*64 + l15*4];
                float4 ot;
                ot.x = __shfl_xor_sync(0xffffffffu, v.x, 16);
                ot.y = __shfl_xor_sync(0xffffffffu, v.y, 16);
                ot.z = __shfl_xor_sync(0xffffffffu, v.z, 16);
                ot.w = __shfl_xor_sync(0xffffffffu, v.w, 16);
                int tb = tseg*64 + l15*4;
                if (half == 0) {                 // v=row c, ot=row c+1 -> hi
                    Xhi[(tb+0)*34 + c2] = pkbf(v.x, ot.x);
                    Xhi[(tb+1)*34 + c2] = pkbf(v.y, ot.y);
                    Xhi[(tb+2)*34 + c2] = pkbf(v.z, ot.z);
                    Xhi[(tb+3)*34 + c2] = pkbf(v.w, ot.w);
                } else {                         // v=row c+1, ot=row c -> lo
                    Xlo[(tb+0)*34 + c2] = pkbf(bfres(ot.x), bfres(v.x));
                    Xlo[(tb+1)*34 + c2] = pkbf(bfres(ot.y), bfres(v.y));
                    Xlo[(tb+2)*34 + c2] = pkbf(bfres(ot.z), bfres(v.z));
                    Xlo[(tb+3)*34 + c2] = pkbf(bfres(ot.w), bfres(v.w));
                }
            }
        }
        CPWAIT0;                                 // W landed (no-op after kc=0)
        __syncthreads();

        #pragma unroll
        for (int k16 = 0; k16 < 4; k16++) {      // 16-c mma steps
            unsigned ah[2][4], al[2][4], bh[4][2], bl[4][2];
            const int cb = (kc*64 + k16*16 + m4*2)*2;   // byte col in W row
            #pragma unroll
            for (int mt=0; mt<2; mt++){
                int ol = ow + mt*16 + l4;
                const char* Wh = psm + PW_HI + ol*WSTR + cb;
                const char* Wl = psm + PW_LO + ol*WSTR + cb;
                ah[mt][0] = *(const unsigned*)(Wh);
                ah[mt][1] = *(const unsigned*)(Wh + 8*WSTR);
                ah[mt][2] = *(const unsigned*)(Wh + 16);
                ah[mt][3] = *(const unsigned*)(Wh + 8*WSTR + 16);
                al[mt][0] = *(const unsigned*)(Wl);
                al[mt][1] = *(const unsigned*)(Wl + 8*WSTR);
                al[mt][2] = *(const unsigned*)(Wl + 16);
                al[mt][3] = *(const unsigned*)(Wl + 8*WSTR + 16);
            }
            #pragma unroll
            for (int nt=0; nt<4; nt++){
                int trow = twl + nt*8 + l4;
                int c2 = k16*8 + m4;
                bh[nt][0] = Xhi[trow*34 + c2];
                bh[nt][1] = Xhi[trow*34 + c2 + 4];
                bl[nt][0] = Xlo[trow*34 + c2];
                bl[nt][1] = Xlo[trow*34 + c2 + 4];
            }
            #pragma unroll
            for (int mt=0; mt<2; mt++)
                #pragma unroll
                for (int nt=0; nt<4; nt++){
                    MMA_BF16(acc[mt][nt], ah[mt], bh[nt]);
                    MMA_BF16(acc[mt][nt], ah[mt], bl[nt]);
                    MMA_BF16(acc[mt][nt], al[mt], bh[nt]);
                }
        }
    }

    // ---- epilogue ----
    if (o0 < 128) {          // q/k: write transposed [o][t], q scaled 0.125
        float sc = (o0 == 0) ? 0.125f : 1.f;
        #pragma unroll
        for (int mt=0; mt<2; mt++)
            #pragma unroll
            for (int h=0; h<2; h++){
                int o = o0 + ow + mt*16 + l4 + 8*h;
                float bi = g_bf[o];
                float* dst = &g_qkT[((size_t)b*128 + o)*T_];
                #pragma unroll
                for (int nt=0; nt<4; nt++){
                    int t = t0 + twl + nt*8 + m4*2;
                    float2 vv;
                    vv.x = fmaxf(acc[mt][nt][2*h]   + bi, 0.f)*sc;
                    vv.y = fmaxf(acc[mt][nt][2*h+1] + bi, 0.f)*sc;
                    *(float2*)&dst[t] = vv;
                }
            }
    } else {                 // v: smem transpose -> coalesced [t][384]
        __syncthreads();
        #pragma unroll
        for (int mt=0; mt<2; mt++)
            #pragma unroll
            for (int h=0; h<2; h++){
                int ol = ow + mt*16 + l4 + 8*h;
                float bi = g_bf[o0 + ol];
                #pragma unroll
                for (int nt=0; nt<4; nt++){
                    int tl = twl + nt*8 + m4*2;
                    Vst[tl*68 + ol]     = fmaxf(acc[mt][nt][2*h]   + bi, 0.f);
                    Vst[(tl+1)*68 + ol] = fmaxf(acc[mt][nt][2*h+1] + bi, 0.f);
                }
            }
        __syncthreads();
        #pragma unroll
        for (int it=0; it<8; it++){
            int idx = tid + it*256;
            int t = idx>>4, og = (idx&15)*4;
            float4 v = *(const float4*)&Vst[t*68 + og];
            *(float4*)&g_qkv[((size_t)b*T_ + t0 + t)*OCH + o0 + og] = v;
        }
    }
}

// ---------------------------------------------------------------------------
// Denominator: batch 0, 16-row tiles, grid 128, 256 thr (warp = 2 rows).
// ---------------------------------------------------------------------------
__global__ __launch_bounds__(256) void denom_k()
{
    __shared__ float Ss[16*SSTR];
    __shared__ float Qp[64*16];
    __shared__ float Kt[2*64*32];
    const int t0 = blockIdx.x*16;
    const int tid = threadIdx.x, warp = tid>>5, lane = tid&31;
    const int r0 = warp*2;
    const int sbase = t0 - DEPTH_;
    const int jmin = (t0 < DEPTH_) ? DEPTH_ - t0 : 0;
    const float* qT = g_qkT;     // batch 0
    const unsigned qp_u = smem_u32(Qp), kt_u = smem_u32(Kt);

    { int d = tid>>2, c4 = (tid&3)*4;
      cpa16(qp_u + (unsigned)(d*16 + c4)*4u, qT + (size_t)d*T_ + t0 + c4); }
    const int chs = jmin >> 5;
    #pragma unroll
    for (int i=0;i<2;i++){
        int f = tid + i*256, d = f>>3, c4 = (f&7)*4;
        cpa16(kt_u + (unsigned)((chs&1)*2048 + d*32 + c4)*4u,
              qT + (size_t)(64+d)*T_ + sbase + chs*32 + c4);
    }
    CPCOMMIT;

    for (int ch = chs; ch < 9; ch++) {
        CPWAIT0; __syncthreads();
        if (ch + 1 < 9) {
            #pragma unroll
            for (int i=0;i<2;i++){
                int f = tid + i*256, d = f>>3, c4 = (f&7)*4;
                cpa16(kt_u + (unsigned)(((ch+1)&1)*2048 + d*32 + c4)*4u,
                      qT + (size_t)(64+d)*T_ + sbase + (ch+1)*32 + c4);
            }
            CPCOMMIT;
        }
        const float* Kb = Kt + (ch&1)*2048;
        u64t a0 = 0ull;
        #pragma unroll 8
        for (int d = 0; d < 64; d++) {
            u64t qq = *(const u64t*)&Qp[d*16 + r0];
            u64t kk = dup2(Kb[d*32 + lane]);
            fma2(a0, qq, kk);
        }
        float f0,f1; unpk(a0,f0,f1);
        int c = ch*32 + lane;
        Ss[(r0+0)*SSTR+c]=f0; Ss[(r0+1)*SSTR+c]=f1;
    }
    __syncthreads();

    {
        int r = tid>>4, g = tid&15, t = t0 + r;
        int jlo = (r+1 > jmin) ? r+1 : jmin;
        int jhi = r + DEPTH_;
        float mx = 0.f;
        for (int j = jlo + g; j <= jhi; j += 16)
            mx = fmaxf(mx, Ss[r*SSTR + j]);
        mx = fmaxf(mx, __shfl_xor_sync(0xffffffffu, mx, 1));
        mx = fmaxf(mx, __shfl_xor_sync(0xffffffffu, mx, 2));
        mx = fmaxf(mx, __shfl_xor_sync(0xffffffffu, mx, 4));
        mx = fmaxf(mx, __shfl_xor_sync(0xffffffffu, mx, 8));
        float s = 0.f;
        for (int j = jlo + g; j <= jhi; j += 16)
            s += __expf(Ss[r*SSTR + j] - mx);
        s += __shfl_xor_sync(0xffffffffu, s, 1);
        s += __shfl_xor_sync(0xffffffffu, s, 2);
        s += __shfl_xor_sync(0xffffffffu, s, 4);
        s += __shfl_xor_sync(0xffffffffu, s, 8);
        if (g == 0) g_denom[t] = s + 1e-30f;
    }
}

// ---------------------------------------------------------------------------
// Banded attention: 64-row tile, 512 thr, 2 CTA/SM (R11 structure).
// ---------------------------------------------------------------------------
__global__ __launch_bounds__(512,2) void attn_k(const float* __restrict__ x,
                                                float* __restrict__ y)
{
    extern __shared__ float sm[];
    float* Ss = sm;                 // [64][322]
    float* Qp = sm + SS_F;          // [64 d][64 t]
    float* Kt = Qp + 4096;          // [64 d][32 c]
    float* Vs = sm + SS_F;          // [16 s][256 c] (alias Qp)

    const int t0 = blockIdx.x*64;
    const int b  = blockIdx.y;
    const int tid = threadIdx.x, warp = tid>>5, lane = tid&31;
    const int r0 = warp*4;
    const int sbase = t0 - DEPTH_;
    const int jmin = (t0 < DEPTH_) ? DEPTH_ - t0 : 0;
    const float* qT = g_qkT + (size_t)b*128*T_;
    const unsigned qp_u = smem_u32(Qp);

    #pragma unroll
    for (int i=0;i<2;i++){
        int u = tid + i*512, d = u>>4, c4 = u&15;
        cpa16(qp_u + (unsigned)(d*64 + c4*4)*4u, qT + (size_t)d*T_ + t0 + c4*4);
    }
    CPCOMMIT;

    const int chs = jmin >> 5;
    const int kd = tid>>3, kc4 = (tid&7)*4;
    float4 kreg = *(const float4*)&qT[(size_t)(64+kd)*T_ + sbase + chs*32 + kc4];
    CPWAIT0;

    for (int ch = chs; ch < 10; ch++) {
        __syncthreads();
        *(float4*)&Kt[kd*32 + kc4] = kreg;
        if (ch + 1 < 10)
            kreg = *(const float4*)&qT[(size_t)(64+kd)*T_ + sbase + (ch+1)*32 + kc4];
        __syncthreads();
        u64t a0 = 0ull, a1 = 0ull;
        #pragma unroll 8
        for (int d = 0; d < 64; d++) {
            float4 qf = *(const float4*)&Qp[d*64 + r0];
            ulonglong2 qq = *(ulonglong2*)&qf;
            u64t kk = dup2(Kt[d*32 + lane]);
            fma2(a0, qq.x, kk); fma2(a1, qq.y, kk);
        }
        float f0,f1,f2,f3; unpk(a0,f0,f1); unpk(a1,f2,f3);
        int c = ch*32 + lane;
        Ss[(r0+0)*SSTR+c]=f0; Ss[(r0+1)*SSTR+c]=f1;
        Ss[(r0+2)*SSTR+c]=f2; Ss[(r0+3)*SSTR+c]=f3;
    }
    __syncthreads();

    const int ch16 = jmin >> 4;
    const int vrow = tid>>6, vc4 = (tid&63)*4;
    float4 vr0 = *(const float4*)&g_qkv[((size_t)b*T_ + sbase + ch16*16 + vrow)*OCH + 128 + vc4];
    float4 vr1 = *(const float4*)&g_qkv[((size_t)b*T_ + sbase + ch16*16 + vrow + 8)*OCH + 128 + vc4];

    {
        int r = tid>>3, g = tid&7, t = t0 + r;
        int jlo = (r+1 > jmin) ? r+1 : jmin;
        int jhi = r + DEPTH_;
        float mx = 0.f;
        for (int j = jlo + g; j <= jhi; j += 8)
            mx = fmaxf(mx, Ss[r*SSTR + j]);
        mx = fmaxf(mx, __shfl_xor_sync(0xffffffffu, mx, 1));
        mx = fmaxf(mx, __shfl_xor_sync(0xffffffffu, mx, 2));
        mx = fmaxf(mx, __shfl_xor_sync(0xffffffffu, mx, 4));
        float invd = 1.f / g_denom[t];
        for (int j = g; j < 320; j += 8) {
            float v = Ss[r*SSTR + j];
            Ss[r*SSTR + j] = (j >= jlo && j <= jhi) ? __expf(v - mx)*invd : 0.f;
        }
    }

    const int rg = warp >> 1, cg = warp & 1;
    const int r0p = rg * 8;
    const int cL = cg*128 + lane*4;
    const int jAw0 = (r0p+1 > jmin) ? r0p+1 : jmin;
    const int jAw = jAw0 & ~1;
    const int jBw = r0p + 7 + DEPTH_;
    u64t acc[8][2];
    #pragma unroll
    for (int i=0;i<8;i++){ acc[i][0]=0ull; acc[i][1]=0ull; }

    for (int ch = ch16; ch < 20; ch++) {
        __syncthreads();
        *(float4*)&Vs[vrow*256 + vc4]       = vr0;
        *(float4*)&Vs[(vrow+8)*256 + vc4]   = vr1;
        if (ch + 1 < 20) {
            vr0 = *(const float4*)&g_qkv[((size_t)b*T_ + sbase + (ch+1)*16 + vrow)*OCH + 128 + vc4];
            vr1 = *(const float4*)&g_qkv[((size_t)b*T_ + sbase + (ch+1)*16 + vrow + 8)*OCH + 128 + vc4];
        }
        __syncthreads();
        int c0 = ch*16;
        int bs = (c0 > jAw) ? c0 : jAw;
        int be = (c0+14 < jBw) ? c0+14 : jBw;
        for (int j2 = bs; j2 <= be; j2 += 2) {
            int lr = j2 - c0;
            float4 v0 = *(const float4*)&Vs[lr*256 + cL];
            float4 v1 = *(const float4*)&Vs[(lr+1)*256 + cL];
            ulonglong2 vp0 = *(ulonglong2*)&v0, vp1 = *(ulonglong2*)&v1;
            #pragma unroll
            for (int i = 0; i < 8; i += 2) {
                float2 pa = *(const float2*)&Ss[(r0p+i)*SSTR + j2];
                float2 pb = *(const float2*)&Ss[(r0p+i+1)*SSTR + j2];
                u64t da = dup2(pa.x), db = dup2(pb.x);
                fma2(acc[i][0],   da, vp0.x); fma2(acc[i][1],   da, vp0.y);
                fma2(acc[i+1][0], db, vp0.x); fma2(acc[i+1][1], db, vp0.y);
                da = dup2(pa.y); db = dup2(pb.y);
                fma2(acc[i][0],   da, vp1.x); fma2(acc[i][1],   da, vp1.y);
                fma2(acc[i+1][0], db, vp1.x); fma2(acc[i+1][1], db, vp1.y);
            }
        }
    }

    float o_[8][4];
    #pragma unroll
    for (int i=0;i<8;i++){
        unpk(acc[i][0], o_[i][0], o_[i][1]);
        unpk(acc[i][1], o_[i][2], o_[i][3]);
    }
    #pragma unroll
    for (int k=0;k<4;k++){
        size_t gi = ((size_t)b*C_ + cL + k)*T_ + t0 + r0p;
        float4 xa = *(const float4*)&x[gi];
        float4 o4 = make_float4(xa.x + o_[0][k], xa.y + o_[1][k],
                                xa.z + o_[2][k], xa.w + o_[3][k]);
        *(float4*)&y[gi] = o4;
        float4 xb = *(const float4*)&x[gi + 4];
        float4 o5 = make_float4(xb.x + o_[4][k], xb.y + o_[5][k],
                                xb.z + o_[6][k], xb.w + o_[7][k]);
        *(float4*)&y[gi + 4] = o5;
    }
}

// ---------------------------------------------------------------------------
extern "C" void kernel_launch(void* const* d_in, const int* in_sizes, int n_in,
                              void* d_out, int out_size)
{
    const float* x   = (const float*)d_in[0];
    const float* kW  = (const float*)d_in[1];
    const float* kb  = (const float*)d_in[2];
    const float* kg  = (const float*)d_in[3];
    const float* kbe = (const float*)d_in[4];
    const float* kmu = (const float*)d_in[5];
    const float* kva = (const float*)d_in[6];
    const float* qW  = (const float*)d_in[7];
    const float* qb  = (const float*)d_in[8];
    const float* qg  = (const float*)d_in[9];
    const float* qbe = (const float*)d_in[10];
    const float* qmu = (const float*)d_in[11];
    const float* qva = (const float*)d_in[12];
    const float* vW  = (const float*)d_in[13];
    const float* vb  = (const float*)d_in[14];
    const float* vg  = (const float*)d_in[15];
    const float* vbe = (const float*)d_in[16];
    const float* vmu = (const float*)d_in[17];
    const float* vva = (const float*)d_in[18];
    float* y = (float*)d_out;

    cudaFuncSetAttribute(proj_t, cudaFuncAttributeMaxDynamicSharedMemorySize, PJ_SMEM);
    cudaFuncSetAttribute(attn_k, cudaFuncAttributeMaxDynamicSharedMemorySize, SM_F*(int)sizeof(float));

    fold_k<<<C_, OCH>>>(kW,kb,kg,kbe,kmu,kva, qW,qb,qg,qbe,qmu,qva, vW,vb,vg,vbe,vmu,vva);
    proj_t<<<dim3(T_/128, OCH/64, B_), 256, PJ_SMEM>>>(x);
    denom_k<<<T_/16, 256>>>();
    attn_k<<<dim3(T_/64, B_), 512, SM_F*sizeof(float)>>>(x, y);
}

// round 17
// speedup vs baseline: 1.2331x; 1.0521x over previous
#include <cuda_runtime.h>
#include <cuda_bf16.h>
#include <math.h>

#define B_ 8
#define C_ 256
#define T_ 2048
#define DEPTH_ 256
#define OCH 384
#define SSTR 322                /* even -> 8B-aligned paired loads */
#define SS_F (64*SSTR)
#define SM_F (SS_F + 6144)      /* 107008 B -> 2 CTA/SM */

/* proj_t smem layout (bytes) */
#define WSTR 528
#define PW_HI 0
#define PW_LO 33792
#define PX_HI 67584
#define PX_LO 84992
#define PJ_SMEM 102400          /* 100 KB -> 2 CTA/SM */

typedef unsigned long long u64t;

__device__ __nv_bfloat16 g_Whi[OCH*C_];    // [o][c] bf16 hi
__device__ __nv_bfloat16 g_Wlo[OCH*C_];    // [o][c] bf16 lo
__device__ __nv_bfloat16 g_vThi[B_*256*T_]; // V [b][c][t] bf16 hi
__device__ __nv_bfloat16 g_vTlo[B_*256*T_]; // V [b][c][t] bf16 lo
__device__ float g_bf[OCH];
__device__ float g_qkT[B_*128*T_];    // [b][o][t]: o<64 q*0.125, o>=64 k
__device__ float g_denom[T_];

static __device__ __forceinline__ u64t pk2(float a,float b){u64t r;asm("mov.b64 %0,{%1,%2};":"=l"(r):"f"(a),"f"(b));return r;}
static __device__ __forceinline__ u64t dup2(float a){return pk2(a,a);}
static __device__ __forceinline__ void fma2(u64t&d,u64t a,u64t b){asm("fma.rn.f32x2 %0,%1,%2,%3;":"=l"(d):"l"(a),"l"(b),"l"(d));}
static __device__ __forceinline__ void unpk(u64t v,float&x,float&y){asm("mov.b64 {%0,%1},%2;":"=f"(x),"=f"(y):"l"(v));}
static __device__ __forceinline__ unsigned smem_u32(const void* p){
    unsigned a; asm("{ .reg .u64 t; cvta.to.shared.u64 t, %1; cvt.u32.u64 %0, t; }":"=r"(a):"l"(p)); return a;
}
static __device__ __forceinline__ void cpa16(unsigned dst, const void* src){
    asm volatile("cp.async.cg.shared.global [%0], [%1], 16;" :: "r"(dst), "l"(src));
}
#define CPCOMMIT asm volatile("cp.async.commit_group;" ::: "memory")
#define CPWAIT0  asm volatile("cp.async.wait_group 0;" ::: "memory")

static __device__ __forceinline__ unsigned pkbf(float a, float b){
    return (unsigned)__bfloat16_as_ushort(__float2bfloat16_rn(a))
         | ((unsigned)__bfloat16_as_ushort(__float2bfloat16_rn(b)) << 16);
}
static __device__ __forceinline__ float bfres(float a){
    return a - __bfloat162float(__float2bfloat16_rn(a));
}
#define MMA_BF16(d,a,b2) asm volatile( \
    "mma.sync.aligned.m16n8k16.row.col.f32.bf16.bf16.f32 " \
    "{%0,%1,%2,%3},{%4,%5,%6,%7},{%8,%9},{%0,%1,%2,%3};" \
    : "+f"((d)[0]),"+f"((d)[1]),"+f"((d)[2]),"+f"((d)[3]) \
    : "r"((a)[0]),"r"((a)[1]),"r"((a)[2]),"r"((a)[3]),"r"((b2)[0]),"r"((b2)[1]))

// ---------------------------------------------------------------------------
__global__ void fold_k(
    const float* __restrict__ kW,const float* __restrict__ kb,const float* __restrict__ kg,
    const float* __restrict__ kbe,const float* __restrict__ kmu,const float* __restrict__ kva,
    const float* __restrict__ qW,const float* __restrict__ qb,const float* __restrict__ qg,
    const float* __restrict__ qbe,const float* __restrict__ qmu,const float* __restrict__ qva,
    const float* __restrict__ vW,const float* __restrict__ vb,const float* __restrict__ vg,
    const float* __restrict__ vbe,const float* __restrict__ vmu,const float* __restrict__ vva)
{
    int c = blockIdx.x, o = threadIdx.x;
    const float *W,*bb,*gg,*be,*mu,*va; int oo;
    if (o < 64)       { W=qW;bb=qb;gg=qg;be=qbe;mu=qmu;va=qva;oo=o; }
    else if (o < 128) { W=kW;bb=kb;gg=kg;be=kbe;mu=kmu;va=kva;oo=o-64; }
    else              { W=vW;bb=vb;gg=vg;be=vbe;mu=vmu;va=vva;oo=o-128; }
    float inv = gg[oo]*rsqrtf(va[oo]+1e-5f);
    float w = W[oo*C_+c]*inv;
    __nv_bfloat16 hi = __float2bfloat16_rn(w);
    g_Whi[o*C_+c] = hi;
    g_Wlo[o*C_+c] = __float2bfloat16_rn(w - __bfloat162float(hi));
    if (c == 0) g_bf[o] = (bb[oo]-mu[oo])*inv + be[oo];
}

// ---------------------------------------------------------------------------
// Projection via mma.sync bf16 hi/lo split. CTA: 128 t x 64 o, 256 thr.
// q/k -> g_qkT fp32 [o][t]; v -> g_vThi/lo bf16 [c][t].
// ---------------------------------------------------------------------------
__global__ __launch_bounds__(256) void proj_t(const float* __restrict__ x)
{
    extern __shared__ char psm[];
    unsigned* Xhi = (unsigned*)(psm + PX_HI);    // [128 t][34] bf16x2 c-pairs
    unsigned* Xlo = (unsigned*)(psm + PX_LO);

    const int t0 = blockIdx.x*128, o0 = blockIdx.y*64, b = blockIdx.z;
    const int tid = threadIdx.x, w = tid>>5, lane = tid&31;
    const int ow = (w&1)*32;                     // warp o base (local)
    const int twl = (w>>1)*32;                   // warp t base (local)
    const int l4 = lane>>2, m4 = lane&3;
    const unsigned sb = smem_u32(psm);

    // stage W tile (hi+lo, 64 o x 256 c) once, coalesced
    {
        const char* whs = (const char*)(g_Whi + (size_t)o0*C_);
        const char* wls = (const char*)(g_Wlo + (size_t)o0*C_);
        #pragma unroll
        for (int i=0;i<8;i++){
            int idx = tid + i*256;
            int row = idx>>5, c16 = idx&31;
            cpa16(sb + PW_HI + row*WSTR + c16*16, whs + row*512 + c16*16);
            cpa16(sb + PW_LO + row*WSTR + c16*16, wls + row*512 + c16*16);
        }
        CPCOMMIT;
    }

    float acc[2][4][4];
    #pragma unroll
    for (int mt=0;mt<2;mt++)
        #pragma unroll
        for (int nt=0;nt<4;nt++)
            #pragma unroll
            for (int i=0;i<4;i++) acc[mt][nt][i] = 0.f;

    for (int kc = 0; kc < 4; kc++) {
        __syncthreads();
        {   // stage x chunk as bf16x2 hi/lo pairs
            int half = lane>>4, l15 = lane&15;
            #pragma unroll
            for (int it=0; it<8; it++){
                int task = w + it*8;
                int c2 = task & 31, tseg = task >> 5;
                int c = kc*64 + c2*2 + half;
                float4 v = *(const float4*)&x[((size_t)b*C_ + c)*T_ + t0 + tseg*64 + l15*4];
                float4 ot;
                ot.x = __shfl_xor_sync(0xffffffffu, v.x, 16);
                ot.y = __shfl_xor_sync(0xffffffffu, v.y, 16);
                ot.z = __shfl_xor_sync(0xffffffffu, v.z, 16);
                ot.w = __shfl_xor_sync(0xffffffffu, v.w, 16);
                int tb = tseg*64 + l15*4;
                if (half == 0) {
                    Xhi[(tb+0)*34 + c2] = pkbf(v.x, ot.x);
                    Xhi[(tb+1)*34 + c2] = pkbf(v.y, ot.y);
                    Xhi[(tb+2)*34 + c2] = pkbf(v.z, ot.z);
                    Xhi[(tb+3)*34 + c2] = pkbf(v.w, ot.w);
                } else {
                    Xlo[(tb+0)*34 + c2] = pkbf(bfres(ot.x), bfres(v.x));
                    Xlo[(tb+1)*34 + c2] = pkbf(bfres(ot.y), bfres(v.y));
                    Xlo[(tb+2)*34 + c2] = pkbf(bfres(ot.z), bfres(v.z));
                    Xlo[(tb+3)*34 + c2] = pkbf(bfres(ot.w), bfres(v.w));
                }
            }
        }
        CPWAIT0;
        __syncthreads();

        #pragma unroll
        for (int k16 = 0; k16 < 4; k16++) {
            unsigned ah[2][4], al[2][4], bh[4][2], bl[4][2];
            const int cb = (kc*64 + k16*16 + m4*2)*2;
            #pragma unroll
            for (int mt=0; mt<2; mt++){
                int ol = ow + mt*16 + l4;
                const char* Wh = psm + PW_HI + ol*WSTR + cb;
                const char* Wl = psm + PW_LO + ol*WSTR + cb;
                ah[mt][0] = *(const unsigned*)(Wh);
                ah[mt][1] = *(const unsigned*)(Wh + 8*WSTR);
                ah[mt][2] = *(const unsigned*)(Wh + 16);
                ah[mt][3] = *(const unsigned*)(Wh + 8*WSTR + 16);
                al[mt][0] = *(const unsigned*)(Wl);
                al[mt][1] = *(const unsigned*)(Wl + 8*WSTR);
                al[mt][2] = *(const unsigned*)(Wl + 16);
                al[mt][3] = *(const unsigned*)(Wl + 8*WSTR + 16);
            }
            #pragma unroll
            for (int nt=0; nt<4; nt++){
                int trow = twl + nt*8 + l4;
                int c2 = k16*8 + m4;
                bh[nt][0] = Xhi[trow*34 + c2];
                bh[nt][1] = Xhi[trow*34 + c2 + 4];
                bl[nt][0] = Xlo[trow*34 + c2];
                bl[nt][1] = Xlo[trow*34 + c2 + 4];
            }
            #pragma unroll
            for (int mt=0; mt<2; mt++)
                #pragma unroll
                for (int nt=0; nt<4; nt++){
                    MMA_BF16(acc[mt][nt], ah[mt], bh[nt]);
                    MMA_BF16(acc[mt][nt], ah[mt], bl[nt]);
                    MMA_BF16(acc[mt][nt], al[mt], bh[nt]);
                }
        }
    }

    // ---- epilogue ----
    if (o0 < 128) {          // q/k -> fp32 [o][t], q scaled 0.125
        float sc = (o0 == 0) ? 0.125f : 1.f;
        #pragma unroll
        for (int mt=0; mt<2; mt++)
            #pragma unroll
            for (int h=0; h<2; h++){
                int o = o0 + ow + mt*16 + l4 + 8*h;
                float bi = g_bf[o];
                float* dst = &g_qkT[((size_t)b*128 + o)*T_];
                #pragma unroll
                for (int nt=0; nt<4; nt++){
                    int t = t0 + twl + nt*8 + m4*2;
                    float2 vv;
                    vv.x = fmaxf(acc[mt][nt][2*h]   + bi, 0.f)*sc;
                    vv.y = fmaxf(acc[mt][nt][2*h+1] + bi, 0.f)*sc;
                    *(float2*)&dst[t] = vv;
                }
            }
    } else {                 // v -> bf16 hi/lo [c][t]
        #pragma unroll
        for (int mt=0; mt<2; mt++)
            #pragma unroll
            for (int h=0; h<2; h++){
                int o = o0 + ow + mt*16 + l4 + 8*h;
                float bi = g_bf[o];
                int c = o - 128;
                __nv_bfloat16* dh = g_vThi + ((size_t)b*256 + c)*T_;
                __nv_bfloat16* dl = g_vTlo + ((size_t)b*256 + c)*T_;
                #pragma unroll
                for (int nt=0; nt<4; nt++){
                    int t = t0 + twl + nt*8 + m4*2;
                    float v0 = fmaxf(acc[mt][nt][2*h]   + bi, 0.f);
                    float v1 = fmaxf(acc[mt][nt][2*h+1] + bi, 0.f);
                    *(unsigned*)&dh[t] = pkbf(v0, v1);
                    *(unsigned*)&dl[t] = pkbf(bfres(v0), bfres(v1));
                }
            }
    }
}

// ---------------------------------------------------------------------------
// Denominator: batch 0, 16-row tiles, grid 128, 256 thr (warp = 2 rows).
// ---------------------------------------------------------------------------
__global__ __launch_bounds__(256) void denom_k()
{
    __shared__ float Ss[16*SSTR];
    __shared__ float Qp[64*16];
    __shared__ float Kt[2*64*32];
    const int t0 = blockIdx.x*16;
    const int tid = threadIdx.x, warp = tid>>5, lane = tid&31;
    const int r0 = warp*2;
    const int sbase = t0 - DEPTH_;
    const int jmin = (t0 < DEPTH_) ? DEPTH_ - t0 : 0;
    const float* qT = g_qkT;     // batch 0
    const unsigned qp_u = smem_u32(Qp), kt_u = smem_u32(Kt);

    { int d = tid>>2, c4 = (tid&3)*4;
      cpa16(qp_u + (unsigned)(d*16 + c4)*4u, qT + (size_t)d*T_ + t0 + c4); }
    const int chs = jmin >> 5;
    #pragma unroll
    for (int i=0;i<2;i++){
        int f = tid + i*256, d = f>>3, c4 = (f&7)*4;
        cpa16(kt_u + (unsigned)((chs&1)*2048 + d*32 + c4)*4u,
              qT + (size_t)(64+d)*T_ + sbase + chs*32 + c4);
    }
    CPCOMMIT;

    for (int ch = chs; ch < 9; ch++) {
        CPWAIT0; __syncthreads();
        if (ch + 1 < 9) {
            #pragma unroll
            for (int i=0;i<2;i++){
                int f = tid + i*256, d = f>>3, c4 = (f&7)*4;
                cpa16(kt_u + (unsigned)(((ch+1)&1)*2048 + d*32 + c4)*4u,
                      qT + (size_t)(64+d)*T_ + sbase + (ch+1)*32 + c4);
            }
            CPCOMMIT;
        }
        const float* Kb = Kt + (ch&1)*2048;
        u64t a0 = 0ull;
        #pragma unroll 8
        for (int d = 0; d < 64; d++) {
            u64t qq = *(const u64t*)&Qp[d*16 + r0];
            u64t kk = dup2(Kb[d*32 + lane]);
            fma2(a0, qq, kk);
        }
        float f0,f1; unpk(a0,f0,f1);
        int c = ch*32 + lane;
        Ss[(r0+0)*SSTR+c]=f0; Ss[(r0+1)*SSTR+c]=f1;
    }
    __syncthreads();

    {
        int r = tid>>4, g = tid&15, t = t0 + r;
        int jlo = (r+1 > jmin) ? r+1 : jmin;
        int jhi = r + DEPTH_;
        float mx = 0.f;
        for (int j = jlo + g; j <= jhi; j += 16)
            mx = fmaxf(mx, Ss[r*SSTR + j]);
        mx = fmaxf(mx, __shfl_xor_sync(0xffffffffu, mx, 1));
        mx = fmaxf(mx, __shfl_xor_sync(0xffffffffu, mx, 2));
        mx = fmaxf(mx, __shfl_xor_sync(0xffffffffu, mx, 4));
        mx = fmaxf(mx, __shfl_xor_sync(0xffffffffu, mx, 8));
        float s = 0.f;
        for (int j = jlo + g; j <= jhi; j += 16)
            s += __expf(Ss[r*SSTR + j] - mx);
        s += __shfl_xor_sync(0xffffffffu, s, 1);
        s += __shfl_xor_sync(0xffffffffu, s, 2);
        s += __shfl_xor_sync(0xffffffffu, s, 4);
        s += __shfl_xor_sync(0xffffffffu, s, 8);
        if (g == 0) g_denom[t] = s + 1e-30f;
    }
}

// ---------------------------------------------------------------------------
// Banded attention: QK+softmax SIMT (proven), PV via mma.sync bf16 3-pass.
// 64-row tile, 512 thr, 2 CTA/SM. PV: D[c][t] = V^T[c][j] @ P^T[j][t].
// ---------------------------------------------------------------------------
__global__ __launch_bounds__(512,2) void attn_k(const float* __restrict__ x,
                                                float* __restrict__ y)
{
    extern __shared__ float sm[];
    float* Ss = sm;                 // [64][322]
    float* Qp = sm + SS_F;          // [64 d][64 t]   (QK phase)
    float* Kt = Qp + 4096;          // [64 d][32 c]   (QK phase)
    char*  Vh = (char*)(sm + SS_F); // [256 c][48B] bf16 hi (PV phase)
    char*  Vl = Vh + 12288;         // [256 c][48B] bf16 lo

    const int t0 = blockIdx.x*64;
    const int b  = blockIdx.y;
    const int tid = threadIdx.x, warp = tid>>5, lane = tid&31;
    const int r0 = warp*4;
    const int sbase = t0 - DEPTH_;
    const int jmin = (t0 < DEPTH_) ? DEPTH_ - t0 : 0;
    const float* qT = g_qkT + (size_t)b*128*T_;
    const unsigned qp_u = smem_u32(Qp);

    // ---- QK (FFMA2, unchanged) ----
    #pragma unroll
    for (int i=0;i<2;i++){
        int u = tid + i*512, d = u>>4, c4 = u&15;
        cpa16(qp_u + (unsigned)(d*64 + c4*4)*4u, qT + (size_t)d*T_ + t0 + c4*4);
    }
    CPCOMMIT;

    const int chs = jmin >> 5;
    const int kd = tid>>3, kc4 = (tid&7)*4;
    float4 kreg = *(const float4*)&qT[(size_t)(64+kd)*T_ + sbase + chs*32 + kc4];
    CPWAIT0;

    for (int ch = chs; ch < 10; ch++) {
        __syncthreads();
        *(float4*)&Kt[kd*32 + kc4] = kreg;
        if (ch + 1 < 10)
            kreg = *(const float4*)&qT[(size_t)(64+kd)*T_ + sbase + (ch+1)*32 + kc4];
        __syncthreads();
        u64t a0 = 0ull, a1 = 0ull;
        #pragma unroll 8
        for (int d = 0; d < 64; d++) {
            float4 qf = *(const float4*)&Qp[d*64 + r0];
            ulonglong2 qq = *(ulonglong2*)&qf;
            u64t kk = dup2(Kt[d*32 + lane]);
            fma2(a0, qq.x, kk); fma2(a1, qq.y, kk);
        }
        float f0,f1,f2,f3; unpk(a0,f0,f1); unpk(a1,f2,f3);
        int c = ch*32 + lane;
        Ss[(r0+0)*SSTR+c]=f0; Ss[(r0+1)*SSTR+c]=f1;
        Ss[(r0+2)*SSTR+c]=f2; Ss[(r0+3)*SSTR+c]=f3;
    }
    __syncthreads();

    // ---- softmax: P = exp(s-max)/denom inside window, 0 outside ----
    {
        int r = tid>>3, g = tid&7, t = t0 + r;
        int jlo = (r+1 > jmin) ? r+1 : jmin;
        int jhi = r + DEPTH_;
        float mx = 0.f;
        for (int j = jlo + g; j <= jhi; j += 8)
            mx = fmaxf(mx, Ss[r*SSTR + j]);
        mx = fmaxf(mx, __shfl_xor_sync(0xffffffffu, mx, 1));
        mx = fmaxf(mx, __shfl_xor_sync(0xffffffffu, mx, 2));
        mx = fmaxf(mx, __shfl_xor_sync(0xffffffffu, mx, 4));
        float invd = 1.f / g_denom[t];
        for (int j = g; j < 320; j += 8) {
            float v = Ss[r*SSTR + j];
            Ss[r*SSTR + j] = (j >= jlo && j <= jhi) ? __expf(v - mx)*invd : 0.f;
        }
    }

    // ---- PV via mma.sync: warp = 32 c (2 m16) x 32 t (4 n8) ----
    const int cb = (warp>>1)*32;
    const int tb = (warp&1)*32;
    const int l4 = lane>>2, m4 = lane&3;
    const int jAw = (tb+1 > jmin) ? tb+1 : jmin;
    const int jBw = tb + 31 + DEPTH_;
    const int ch16 = jmin >> 4;
    const unsigned vh_u = smem_u32(Vh);
    const char* vhg = (const char*)g_vThi + ((size_t)b*256)*T_*2;
    const char* vlg = (const char*)g_vTlo + ((size_t)b*256)*T_*2;

    float acc[2][4][4];
    #pragma unroll
    for (int mt=0;mt<2;mt++)
        #pragma unroll
        for (int nt=0;nt<4;nt++)
            #pragma unroll
            for (int i=0;i<4;i++) acc[mt][nt][i] = 0.f;

    for (int ch = ch16; ch < 20; ch++) {
        __syncthreads();                         // prev chunk A-reads done
        int s0 = sbase + ch*16;
        {   // stage V chunk: 256 rows x 32B, hi+lo (1024 cp.async)
            #pragma unroll
            for (int i=0;i<2;i++){
                int idx = tid + i*512;
                int c = idx>>2, q = idx&3;
                unsigned dst = vh_u + (unsigned)((q>>1)*12288 + c*48 + (q&1)*16);
                const char* src = ((q>>1) ? vlg : vhg) + ((size_t)c*T_ + s0)*2 + (q&1)*16;
                cpa16(dst, src);
            }
            CPCOMMIT;
        }
        int c0 = ch*16;
        bool active = (c0+15 >= jAw) && (c0 <= jBw);
        unsigned bh[4][2], bl[4][2];
        if (active) {                            // B-frags from Ss (overlaps cp.async)
            #pragma unroll
            for (int nt=0; nt<4; nt++){
                int trow = tb + nt*8 + l4;
                float2 p0 = *(const float2*)&Ss[trow*SSTR + c0 + m4*2];
                float2 p1 = *(const float2*)&Ss[trow*SSTR + c0 + 8 + m4*2];
                bh[nt][0] = pkbf(p0.x, p0.y);
                bh[nt][1] = pkbf(p1.x, p1.y);
                bl[nt][0] = pkbf(bfres(p0.x), bfres(p0.y));
                bl[nt][1] = pkbf(bfres(p1.x), bfres(p1.y));
            }
        }
        CPWAIT0;
        __syncthreads();                         // V chunk visible
        if (active) {
            #pragma unroll
            for (int mt=0; mt<2; mt++){
                unsigned ah[4], al[4];
                int c = cb + mt*16 + l4;
                const char* ph = Vh + c*48 + m4*4;
                const char* pl = Vl + c*48 + m4*4;
                ah[0] = *(const unsigned*)(ph);
                ah[1] = *(const unsigned*)(ph + 8*48);
                ah[2] = *(const unsigned*)(ph + 16);
                ah[3] = *(const unsigned*)(ph + 8*48 + 16);
                al[0] = *(const unsigned*)(pl);
                al[1] = *(const unsigned*)(pl + 8*48);
                al[2] = *(const unsigned*)(pl + 16);
                al[3] = *(const unsigned*)(pl + 8*48 + 16);
                #pragma unroll
                for (int nt=0; nt<4; nt++){
                    MMA_BF16(acc[mt][nt], ah, bh[nt]);
                    MMA_BF16(acc[mt][nt], ah, bl[nt]);
                    MMA_BF16(acc[mt][nt], al, bh[nt]);
                }
            }
        }
    }

    // ---- epilogue: D[c][t] fragments -> y = x + out, float2 stores ----
    #pragma unroll
    for (int mt=0; mt<2; mt++)
        #pragma unroll
        for (int nt=0; nt<4; nt++){
            int c = cb + mt*16 + l4;
            int t = t0 + tb + nt*8 + m4*2;
            size_t gi = ((size_t)b*C_ + c)*T_ + t;
            float2 xa = *(const float2*)&x[gi];
            float2 o2 = make_float2(xa.x + acc[mt][nt][0], xa.y + acc[mt][nt][1]);
            *(float2*)&y[gi] = o2;
            size_t gi8 = gi + (size_t)8*T_;
            float2 xb = *(const float2*)&x[gi8];
            float2 o3 = make_float2(xb.x + acc[mt][nt][2], xb.y + acc[mt][nt][3]);
            *(float2*)&y[gi8] = o3;
        }
}

// ---------------------------------------------------------------------------
extern "C" void kernel_launch(void* const* d_in, const int* in_sizes, int n_in,
                              void* d_out, int out_size)
{
    const float* x   = (const float*)d_in[0];
    const float* kW  = (const float*)d_in[1];
    const float* kb  = (const float*)d_in[2];
    const float* kg  = (const float*)d_in[3];
    const float* kbe = (const float*)d_in[4];
    const float* kmu = (const float*)d_in[5];
    const float* kva = (const float*)d_in[6];
    const float* qW  = (const float*)d_in[7];
    const float* qb  = (const float*)d_in[8];
    const float* qg  = (const float*)d_in[9];
    const float* qbe = (const float*)d_in[10];
    const float* qmu = (const float*)d_in[11];
    const float* qva = (const float*)d_in[12];
    const float* vW  = (const float*)d_in[13];
    const float* vb  = (const float*)d_in[14];
    const float* vg  = (const float*)d_in[15];
    const float* vbe = (const float*)d_in[16];
    const float* vmu = (const float*)d_in[17];
    const float* vva = (const float*)d_in[18];
    float* y = (float*)d_out;

    cudaFuncSetAttribute(proj_t, cudaFuncAttributeMaxDynamicSharedMemorySize, PJ_SMEM);
    cudaFuncSetAttribute(attn_k, cudaFuncAttributeMaxDynamicSharedMemorySize, SM_F*(int)sizeof(float));

    fold_k<<<C_, OCH>>>(kW,kb,kg,kbe,kmu,kva, qW,qb,qg,qbe,qmu,qva, vW,vb,vg,vbe,vmu,vva);
    proj_t<<<dim3(T_/128, OCH/64, B_), 256, PJ_SMEM>>>(x);
    denom_k<<<T_/16, 256>>>();
    attn_k<<<dim3(T_/64, B_), 512, SM_F*sizeof(float)>>>(x, y);
}